// round 4
// baseline (speedup 1.0000x reference)
#include <cuda_runtime.h>
#include <cuda_bf16.h>
#include <math.h>

// ---------------------------------------------------------------------------
// ActorMultiHead: 3-layer shared MLP (tf32 tensor-core GEMMs) + stacked role
// heads + Gaussian log-prob epilogue.
//
// Inputs (metadata order):
//  0 obs      [2048,16,128] f32     7 W2  [1024,1024] f32
//  1 role_ids [2048,16]     i32     8 b2  [1024]      f32
//  2 actions  [2048,16,8]   f32     9 hW1 [2,1024,512] f32
//  3 W0  [130,1024] f32            10 hb1 [2,512]      f32
//  4 b0  [1024]     f32            11 hW2 [2,512,8]    f32
//  5 W1  [1024,1024] f32           12 hb2 [2,8]        f32
//  6 b1  [1024]      f32           13 log_stds [2,8]   f32
// Output: log_probs [2048,16] f32 (32768)
// ---------------------------------------------------------------------------

#define M_TOTAL  32768
#define N_TOTAL  1024
#define BM 128
#define BN 64
#define BK 32
#define AS_STRIDE 36   // BK + 4 pad -> conflict-free A fragment loads
#define BS_STRIDE 72   // BN + 8 pad -> conflict-free B fragment loads

// Scratch (allocation-free: __device__ globals). Ping-pong between layers.
__device__ float g_bufA[M_TOTAL * N_TOTAL];
__device__ float g_bufB[M_TOTAL * N_TOTAL];

__device__ __forceinline__ float tf32_round(float f) {
    unsigned u;
    asm("cvt.rna.tf32.f32 %0, %1;" : "=r"(u) : "f"(f));
    return __uint_as_float(u);
}

__device__ __forceinline__ void mma_tf32(float d[4], const unsigned a[4], const unsigned b[2]) {
    asm("mma.sync.aligned.m16n8k8.row.col.f32.tf32.tf32.f32 "
        "{%0,%1,%2,%3}, {%4,%5,%6,%7}, {%8,%9}, {%0,%1,%2,%3};\n"
        : "+f"(d[0]), "+f"(d[1]), "+f"(d[2]), "+f"(d[3])
        : "r"(a[0]), "r"(a[1]), "r"(a[2]), "r"(a[3]), "r"(b[0]), "r"(b[1]));
}

// MODEA: 0 = plain A[M,K] (lda=K) ; 1 = concat(obs[M,128], onehot(role,2))
// MODEB: 0 = plain W[K,1024]       ; 1 = stacked hW1[2, K, 512] -> [K,1024]
template <int MODEA, int MODEB>
__global__ void __launch_bounds__(256)
gemm_relu_kernel(const float* __restrict__ A,
                 const int*   __restrict__ role_ids,
                 const float* __restrict__ Bmat,
                 const float* __restrict__ bias,   // [1024]
                 float* __restrict__ C,            // [M,1024]
                 int K)
{
    __shared__ float As[BM * AS_STRIDE];
    __shared__ float Bs[BK * BS_STRIDE];

    const int tid  = threadIdx.x;
    const int lane = tid & 31;
    const int warp = tid >> 5;
    const int wm = warp & 3;          // 4 warps along M
    const int wn = warp >> 2;         // 2 warps along N
    const int wrow0 = wm * 32;
    const int wcol0 = wn * 32;
    const int blockM = blockIdx.y * BM;
    const int blockN = blockIdx.x * BN;

    float acc[2][4][4];
#pragma unroll
    for (int mi = 0; mi < 2; mi++)
#pragma unroll
        for (int ni = 0; ni < 4; ni++)
#pragma unroll
            for (int c = 0; c < 4; c++) acc[mi][ni][c] = 0.f;

    const int ktiles = (K + BK - 1) / BK;
    for (int kt = 0; kt < ktiles; kt++) {
        const int k0 = kt * BK;
        // ---- stage A tile [BM x BK], coalesced over k ----
#pragma unroll
        for (int i = 0; i < (BM * BK) / 256; i++) {   // 16 elems/thread
            int idx = tid + i * 256;
            int m  = idx >> 5;
            int kk = idx & 31;
            int gk = k0 + kk;
            int gm = blockM + m;
            float v = 0.f;
            if (MODEA == 0) {
                if (gk < K) v = A[gm * K + gk];
            } else {
                if (gk < 128)      v = A[gm * 128 + gk];
                else if (gk < 130) v = (role_ids[gm] == (gk - 128)) ? 1.f : 0.f;
            }
            As[m * AS_STRIDE + kk] = tf32_round(v);
        }
        // ---- stage B tile [BK x BN], coalesced over n ----
#pragma unroll
        for (int i = 0; i < (BK * BN) / 256; i++) {   // 8 elems/thread
            int idx = tid + i * 256;
            int kk = idx >> 6;
            int n  = idx & 63;
            int gk = k0 + kk;
            int gn = blockN + n;
            float v = 0.f;
            if (gk < K) {
                if (MODEB == 0) {
                    v = Bmat[gk * N_TOTAL + gn];
                } else {
                    int r = gn >> 9, c = gn & 511;
                    v = Bmat[r * (K * 512) + gk * 512 + c];
                }
            }
            Bs[kk * BS_STRIDE + n] = tf32_round(v);
        }
        __syncthreads();

#pragma unroll
        for (int ks = 0; ks < BK / 8; ks++) {
            unsigned a[2][4], b[4][2];
#pragma unroll
            for (int mi = 0; mi < 2; mi++) {
                int ar = wrow0 + mi * 16 + (lane >> 2);
                int ac = ks * 8 + (lane & 3);
                a[mi][0] = __float_as_uint(As[ar * AS_STRIDE + ac]);
                a[mi][1] = __float_as_uint(As[(ar + 8) * AS_STRIDE + ac]);
                a[mi][2] = __float_as_uint(As[ar * AS_STRIDE + ac + 4]);
                a[mi][3] = __float_as_uint(As[(ar + 8) * AS_STRIDE + ac + 4]);
            }
#pragma unroll
            for (int ni = 0; ni < 4; ni++) {
                int br = ks * 8 + (lane & 3);
                int bc = wcol0 + ni * 8 + (lane >> 2);
                b[ni][0] = __float_as_uint(Bs[br * BS_STRIDE + bc]);
                b[ni][1] = __float_as_uint(Bs[(br + 4) * BS_STRIDE + bc]);
            }
#pragma unroll
            for (int mi = 0; mi < 2; mi++)
#pragma unroll
                for (int ni = 0; ni < 4; ni++)
                    mma_tf32(acc[mi][ni], a[mi], b[ni]);
        }
        __syncthreads();
    }

    // ---- epilogue: bias + ReLU ----
#pragma unroll
    for (int mi = 0; mi < 2; mi++) {
#pragma unroll
        for (int ni = 0; ni < 4; ni++) {
            int row = blockM + wrow0 + mi * 16 + (lane >> 2);
            int col = blockN + wcol0 + ni * 8 + 2 * (lane & 3);
            float b0v = bias[col];
            float b1v = bias[col + 1];
            float v0 = acc[mi][ni][0] + b0v;
            float v1 = acc[mi][ni][1] + b1v;
            float v2 = acc[mi][ni][2] + b0v;
            float v3 = acc[mi][ni][3] + b1v;
            C[row * N_TOTAL + col]           = v0 > 0.f ? v0 : 0.f;
            C[row * N_TOTAL + col + 1]       = v1 > 0.f ? v1 : 0.f;
            C[(row + 8) * N_TOTAL + col]     = v2 > 0.f ? v2 : 0.f;
            C[(row + 8) * N_TOTAL + col + 1] = v3 > 0.f ? v3 : 0.f;
        }
    }
}

// ---------------------------------------------------------------------------
// Head layer 2 + tanh + diagonal-Gaussian log prob, role-selected.
// One warp per token; hW2 held transposed in smem ([r][k][m]) so inner LDS is
// broadcast/conflict-free.
// ---------------------------------------------------------------------------
__global__ void __launch_bounds__(256)
head2_logprob_kernel(const float* __restrict__ Z,        // [32768,1024]
                     const int*   __restrict__ role_ids, // [32768]
                     const float* __restrict__ actions,  // [32768,8]
                     const float* __restrict__ hW2,      // [2*512*8]
                     const float* __restrict__ hb2,      // [16]
                     const float* __restrict__ logstd,   // [16]
                     float* __restrict__ out)            // [32768]
{
    __shared__ float sW[2 * 8 * 512];  // [r][k][m]
    __shared__ float sb[16];
    __shared__ float sls[16];

    const int tid = threadIdx.x;
    for (int idx = tid; idx < 8192; idx += 256) {
        int r = idx >> 12;
        int rem = idx & 4095;
        int m = rem >> 3;
        int k = rem & 7;
        sW[r * 4096 + k * 512 + m] = hW2[idx];
    }
    if (tid < 16) { sb[tid] = hb2[tid]; sls[tid] = logstd[tid]; }
    __syncthreads();

    const int warp = tid >> 5;
    const int lane = tid & 31;
    const int t = blockIdx.x * 8 + warp;

    const int role = role_ids[t];
    if (role >= 2) {                 // outside trainable roles -> one_hot==0
        if (lane == 0) out[t] = 0.f;
        return;
    }

    const float* z = Z + (size_t)t * 1024 + role * 512;
    const float* w = sW + role * 4096;

    float s[8];
#pragma unroll
    for (int k = 0; k < 8; k++) s[k] = 0.f;

#pragma unroll
    for (int j = 0; j < 16; j++) {
        int m = lane + j * 32;
        float zv = z[m];
#pragma unroll
        for (int k = 0; k < 8; k++) s[k] += zv * w[k * 512 + m];
    }
#pragma unroll
    for (int k = 0; k < 8; k++) {
#pragma unroll
        for (int off = 16; off; off >>= 1)
            s[k] += __shfl_xor_sync(0xffffffffu, s[k], off);
    }

    if (lane == 0) {
        float lp = 0.f;
#pragma unroll
        for (int k = 0; k < 8; k++) {
            float mean = tanhf(s[k] + sb[role * 8 + k]);
            float ls = sls[role * 8 + k];
            float d = (actions[t * 8 + k] - mean) * expf(-ls);
            lp += -0.5f * d * d - ls - 0.91893853320467274178f; // 0.5*ln(2*pi)
        }
        out[t] = lp;
    }
}

extern "C" void kernel_launch(void* const* d_in, const int* in_sizes, int n_in,
                              void* d_out, int out_size)
{
    const float* obs      = (const float*)d_in[0];
    const int*   role_ids = (const int*)  d_in[1];
    const float* actions  = (const float*)d_in[2];
    const float* W0  = (const float*)d_in[3];
    const float* b0  = (const float*)d_in[4];
    const float* W1  = (const float*)d_in[5];
    const float* b1  = (const float*)d_in[6];
    const float* W2  = (const float*)d_in[7];
    const float* b2  = (const float*)d_in[8];
    const float* hW1 = (const float*)d_in[9];
    const float* hb1 = (const float*)d_in[10];
    const float* hW2 = (const float*)d_in[11];
    const float* hb2 = (const float*)d_in[12];
    const float* lsd = (const float*)d_in[13];
    float* out = (float*)d_out;

    float* bufA = nullptr;
    float* bufB = nullptr;
    cudaGetSymbolAddress((void**)&bufA, g_bufA);
    cudaGetSymbolAddress((void**)&bufB, g_bufB);

    dim3 block(256);
    dim3 grid(N_TOTAL / BN, M_TOTAL / BM);   // (16, 256)

    // L0: x = concat(obs, onehot) @ W0 + b0, relu     -> bufA
    gemm_relu_kernel<1, 0><<<grid, block>>>(obs, role_ids, W0, b0, bufA, 130);
    // L1: bufA @ W1 + b1, relu                        -> bufB
    gemm_relu_kernel<0, 0><<<grid, block>>>(bufA, role_ids, W1, b1, bufB, 1024);
    // L2: bufB @ W2 + b2, relu                        -> bufA
    gemm_relu_kernel<0, 0><<<grid, block>>>(bufB, role_ids, W2, b2, bufA, 1024);
    // Heads layer1 (both roles stacked along N): bufA @ hW1 + hb1, relu -> bufB
    gemm_relu_kernel<0, 1><<<grid, block>>>(bufA, role_ids, hW1, hb1, bufB, 1024);
    // Head layer2 + tanh + Gaussian log-prob, role-selected
    head2_logprob_kernel<<<M_TOTAL / 8, block>>>(bufB, role_ids, actions,
                                                 hW2, hb2, lsd, out);
}

// round 6
// speedup vs baseline: 2.5130x; 2.5130x over previous
#include <cuda_runtime.h>
#include <cuda_bf16.h>
#include <cstdint>
#include <math.h>

// ---------------------------------------------------------------------------
// ActorMultiHead — tf32 tensor-core pipeline, cp.async double-buffered GEMMs.
//
// Pipeline:
//   pack_x : Xp[32768,160] = tf32(concat(obs, onehot(role,2)), zero-pad)
//   pack_w : wp = tf32({W0 padded to [160,1024], W1, W2, hW1 repacked [1024,1024]})
//   gemm x4: 128x128 CTA tile, BK=32, 4 warps (64x64 warp tile),
//            double-buffered cp.async, m16n8k8 tf32 mma, bias+relu(+round) epi
//   head2  : per-token head-2 matvec + tanh + Gaussian log-prob, role select
// ---------------------------------------------------------------------------

#define M_TOTAL  32768
#define BM 128
#define BN 128
#define BK 32
#define AS_STRIDE 36           // 36 ≡ 4 (mod 32): conflict-free A frag LDS
#define BS_STRIDE 136          // 136 ≡ 8 (mod 32): conflict-free B frag LDS
#define ASZ (BM * AS_STRIDE)   // 4608 floats
#define BSZ (BK * BS_STRIDE)   // 4352 floats
#define STG (ASZ + BSZ)        // 8960 floats per stage
#define SMEM_BYTES (2 * STG * 4)   // 71680 B

#define W0P_OFF 0
#define W1_OFF  (160 * 1024)
#define W2_OFF  (W1_OFF + 1024 * 1024)
#define HW1_OFF (W2_OFF + 1024 * 1024)
#define WP_TOTAL (HW1_OFF + 1024 * 1024)

// Scratch (allocation-free __device__ globals)
__device__ float g_bufA[M_TOTAL * 1024];
__device__ float g_bufB[M_TOTAL * 1024];
__device__ float g_xpad[M_TOTAL * 160];
__device__ float g_wp[WP_TOTAL];

__device__ __forceinline__ float tf32_round(float f) {
    unsigned u;
    asm("cvt.rna.tf32.f32 %0, %1;" : "=r"(u) : "f"(f));
    return __uint_as_float(u);
}

__device__ __forceinline__ void mma_tf32(float d[4], const unsigned a[4], const unsigned b[2]) {
    asm("mma.sync.aligned.m16n8k8.row.col.f32.tf32.tf32.f32 "
        "{%0,%1,%2,%3}, {%4,%5,%6,%7}, {%8,%9}, {%0,%1,%2,%3};\n"
        : "+f"(d[0]), "+f"(d[1]), "+f"(d[2]), "+f"(d[3])
        : "r"(a[0]), "r"(a[1]), "r"(a[2]), "r"(a[3]), "r"(b[0]), "r"(b[1]));
}

__device__ __forceinline__ void cp16(unsigned s, const float* g) {
    asm volatile("cp.async.cg.shared.global [%0], [%1], 16;\n" :: "r"(s), "l"(g));
}

// ---------------------------------------------------------------------------
// Prepack kernels
// ---------------------------------------------------------------------------
__global__ void pack_x(const float* __restrict__ obs, const int* __restrict__ roles,
                       float* __restrict__ xp)
{
    const int t = blockIdx.x;
    const int k = threadIdx.x;          // 0..159
    float v = 0.f;
    if (k < 128)      v = obs[t * 128 + k];
    else if (k < 130) v = (roles[t] == (k - 128)) ? 1.f : 0.f;
    xp[t * 160 + k] = tf32_round(v);
}

__global__ void pack_w(const float* __restrict__ W0, const float* __restrict__ W1,
                       const float* __restrict__ W2, const float* __restrict__ hW1,
                       float* __restrict__ wp)
{
    const int idx = blockIdx.x * 256 + threadIdx.x;
    if (idx >= WP_TOTAL) return;
    float v;
    if (idx < W1_OFF) {                        // W0 padded [160,1024]
        int k = idx >> 10, n = idx & 1023;
        v = (k < 130) ? W0[k * 1024 + n] : 0.f;
    } else if (idx < W2_OFF) {
        v = W1[idx - W1_OFF];
    } else if (idx < HW1_OFF) {
        v = W2[idx - W2_OFF];
    } else {                                   // hW1 [2,1024,512] -> [1024,1024]
        int j = idx - HW1_OFF;
        int k = j >> 10, n = j & 1023;
        int r = n >> 9, c = n & 511;
        v = hW1[r * (1024 * 512) + k * 512 + c];
    }
    wp[idx] = tf32_round(v);
}

// ---------------------------------------------------------------------------
// Generic GEMM: C[M,1024] = relu(A[M,K] @ B[K,1024] + bias), data pre-rounded.
// 128 threads, 4 warps (2x2), warp tile 64x64, double-buffered cp.async.
// ---------------------------------------------------------------------------
template <int ROUND>
__global__ void __launch_bounds__(128, 2)
gemm_tc(const float* __restrict__ A, const float* __restrict__ B,
        const float* __restrict__ bias, float* __restrict__ C, int K)
{
    extern __shared__ float smem[];
    const int tid  = threadIdx.x;
    const int lane = tid & 31;
    const int warp = tid >> 5;
    const int wm = warp >> 1;            // 2 warps along M
    const int wn = warp & 1;             // 2 warps along N
    const int blockM = blockIdx.y * BM;
    const int blockN = blockIdx.x * BN;

    const unsigned smemB = (unsigned)__cvta_generic_to_shared(smem);

    // staging thread-invariants: A = 1024 f4 (8/thread), B = 1024 f4 (8/thread)
    const int aRow = tid >> 3, aC = (tid & 7) * 4;
    const int bRow = tid >> 5, bC = (tid & 31) * 4;
    const float* aG0 = A + (blockM + aRow) * K + aC;
    const float* bG0 = B + bRow * 1024 + blockN + bC;
    const unsigned aS0 = smemB + (unsigned)(aRow * AS_STRIDE + aC) * 4u;
    const unsigned bS0 = smemB + (unsigned)(ASZ + bRow * BS_STRIDE + bC) * 4u;

    auto stage = [&](int kt) {
        const unsigned so = (unsigned)(kt & 1) * (STG * 4u);
        const float* ag = aG0 + kt * BK;
        const float* bg = bG0 + kt * BK * 1024;
#pragma unroll
        for (int i = 0; i < 8; i++)
            cp16(aS0 + so + (unsigned)(i * 16 * AS_STRIDE * 4), ag + i * 16 * K);
#pragma unroll
        for (int i = 0; i < 8; i++)
            cp16(bS0 + so + (unsigned)(i * 4 * BS_STRIDE * 4), bg + i * 4 * 1024);
    };

    float acc[4][8][4];
#pragma unroll
    for (int mi = 0; mi < 4; mi++)
#pragma unroll
        for (int ni = 0; ni < 8; ni++)
#pragma unroll
            for (int c = 0; c < 4; c++) acc[mi][ni][c] = 0.f;

    const int ktiles = K >> 5;
    stage(0);
    asm volatile("cp.async.commit_group;\n");

    for (int kt = 0; kt < ktiles; kt++) {
        if (kt + 1 < ktiles) {
            stage(kt + 1);
            asm volatile("cp.async.commit_group;\n");
            asm volatile("cp.async.wait_group 1;\n");
        } else {
            asm volatile("cp.async.wait_group 0;\n");
        }
        __syncthreads();

        const float* as = smem + (kt & 1) * STG;
        const float* bs = as + ASZ;

#pragma unroll
        for (int ks = 0; ks < BK / 8; ks++) {
            unsigned a[4][4], b[8][2];
            const int ac = ks * 8 + (lane & 3);
#pragma unroll
            for (int mi = 0; mi < 4; mi++) {
                const int ar = wm * 64 + mi * 16 + (lane >> 2);
                a[mi][0] = __float_as_uint(as[ar * AS_STRIDE + ac]);
                a[mi][1] = __float_as_uint(as[(ar + 8) * AS_STRIDE + ac]);
                a[mi][2] = __float_as_uint(as[ar * AS_STRIDE + ac + 4]);
                a[mi][3] = __float_as_uint(as[(ar + 8) * AS_STRIDE + ac + 4]);
            }
            const int br  = ks * 8 + (lane & 3);
            const int bc0 = wn * 64 + (lane >> 2);
#pragma unroll
            for (int ni = 0; ni < 8; ni++) {
                b[ni][0] = __float_as_uint(bs[br * BS_STRIDE + bc0 + ni * 8]);
                b[ni][1] = __float_as_uint(bs[(br + 4) * BS_STRIDE + bc0 + ni * 8]);
            }
#pragma unroll
            for (int mi = 0; mi < 4; mi++)
#pragma unroll
                for (int ni = 0; ni < 8; ni++)
                    mma_tf32(acc[mi][ni], a[mi], b[ni]);
        }
        __syncthreads();
    }

    // epilogue: bias + relu (+ tf32 round for inter-layer activations)
#pragma unroll
    for (int ni = 0; ni < 8; ni++) {
        const int col = blockN + wn * 64 + ni * 8 + 2 * (lane & 3);
        const float bb0 = bias[col];
        const float bb1 = bias[col + 1];
#pragma unroll
        for (int mi = 0; mi < 4; mi++) {
            const int row = blockM + wm * 64 + mi * 16 + (lane >> 2);
            float v0 = fmaxf(acc[mi][ni][0] + bb0, 0.f);
            float v1 = fmaxf(acc[mi][ni][1] + bb1, 0.f);
            float v2 = fmaxf(acc[mi][ni][2] + bb0, 0.f);
            float v3 = fmaxf(acc[mi][ni][3] + bb1, 0.f);
            if (ROUND) {
                v0 = tf32_round(v0); v1 = tf32_round(v1);
                v2 = tf32_round(v2); v3 = tf32_round(v3);
            }
            *(float2*)&C[row * 1024 + col]       = make_float2(v0, v1);
            *(float2*)&C[(row + 8) * 1024 + col] = make_float2(v2, v3);
        }
    }
}

// ---------------------------------------------------------------------------
// Head layer 2 + tanh + diagonal-Gaussian log prob, role-selected.
// ---------------------------------------------------------------------------
__global__ void __launch_bounds__(256)
head2_logprob_kernel(const float* __restrict__ Z,        // [32768,1024]
                     const int*   __restrict__ role_ids, // [32768]
                     const float* __restrict__ actions,  // [32768,8]
                     const float* __restrict__ hW2,      // [2*512*8]
                     const float* __restrict__ hb2,      // [16]
                     const float* __restrict__ logstd,   // [16]
                     float* __restrict__ out)            // [32768]
{
    __shared__ float sW[2 * 8 * 512];  // [r][k][m]
    __shared__ float sb[16];
    __shared__ float sls[16];

    const int tid = threadIdx.x;
    for (int idx = tid; idx < 8192; idx += 256) {
        int r = idx >> 12;
        int rem = idx & 4095;
        int m = rem >> 3;
        int k = rem & 7;
        sW[r * 4096 + k * 512 + m] = hW2[idx];
    }
    if (tid < 16) { sb[tid] = hb2[tid]; sls[tid] = logstd[tid]; }
    __syncthreads();

    const int warp = tid >> 5;
    const int lane = tid & 31;
    const int t = blockIdx.x * 8 + warp;

    const int role = role_ids[t];
    if (role >= 2) {
        if (lane == 0) out[t] = 0.f;
        return;
    }

    const float* z = Z + (size_t)t * 1024 + role * 512;
    const float* w = sW + role * 4096;

    float s[8];
#pragma unroll
    for (int k = 0; k < 8; k++) s[k] = 0.f;

#pragma unroll
    for (int j = 0; j < 16; j++) {
        int m = lane + j * 32;
        float zv = z[m];
#pragma unroll
        for (int k = 0; k < 8; k++) s[k] += zv * w[k * 512 + m];
    }
#pragma unroll
    for (int k = 0; k < 8; k++) {
#pragma unroll
        for (int off = 16; off; off >>= 1)
            s[k] += __shfl_xor_sync(0xffffffffu, s[k], off);
    }

    if (lane == 0) {
        float lp = 0.f;
#pragma unroll
        for (int k = 0; k < 8; k++) {
            float mean = tanhf(s[k] + sb[role * 8 + k]);
            float ls = sls[role * 8 + k];
            float d = (actions[t * 8 + k] - mean) * expf(-ls);
            lp += -0.5f * d * d - ls - 0.91893853320467274178f; // 0.5*ln(2*pi)
        }
        out[t] = lp;
    }
}

extern "C" void kernel_launch(void* const* d_in, const int* in_sizes, int n_in,
                              void* d_out, int out_size)
{
    const float* obs      = (const float*)d_in[0];
    const int*   role_ids = (const int*)  d_in[1];
    const float* actions  = (const float*)d_in[2];
    const float* W0  = (const float*)d_in[3];
    const float* b0  = (const float*)d_in[4];
    const float* W1  = (const float*)d_in[5];
    const float* b1  = (const float*)d_in[6];
    const float* W2  = (const float*)d_in[7];
    const float* b2  = (const float*)d_in[8];
    const float* hW1 = (const float*)d_in[9];
    const float* hb1 = (const float*)d_in[10];  // [2,512] = flat [1024] bias
    const float* hW2 = (const float*)d_in[11];
    const float* hb2 = (const float*)d_in[12];
    const float* lsd = (const float*)d_in[13];
    float* out = (float*)d_out;

    float *bufA = nullptr, *bufB = nullptr, *xpad = nullptr, *wp = nullptr;
    cudaGetSymbolAddress((void**)&bufA, g_bufA);
    cudaGetSymbolAddress((void**)&bufB, g_bufB);
    cudaGetSymbolAddress((void**)&xpad, g_xpad);
    cudaGetSymbolAddress((void**)&wp,   g_wp);

    cudaFuncSetAttribute(gemm_tc<1>, cudaFuncAttributeMaxDynamicSharedMemorySize, SMEM_BYTES);
    cudaFuncSetAttribute(gemm_tc<0>, cudaFuncAttributeMaxDynamicSharedMemorySize, SMEM_BYTES);

    // prepack (tf32 rounding hoisted out of GEMM mainloops)
    pack_x<<<M_TOTAL, 160>>>(obs, role_ids, xpad);
    pack_w<<<(WP_TOTAL + 255) / 256, 256>>>(W0, W1, W2, hW1, wp);

    dim3 block(128);
    dim3 grid(1024 / BN, M_TOTAL / BM);   // (8, 256)

    // L0: relu(Xp @ W0p + b0)            -> bufA   (K=160)
    gemm_tc<1><<<grid, block, SMEM_BYTES>>>(xpad, wp + W0P_OFF, b0, bufA, 160);
    // L1: relu(bufA @ W1 + b1)           -> bufB
    gemm_tc<1><<<grid, block, SMEM_BYTES>>>(bufA, wp + W1_OFF, b1, bufB, 1024);
    // L2: relu(bufB @ W2 + b2)           -> bufA
    gemm_tc<1><<<grid, block, SMEM_BYTES>>>(bufB, wp + W2_OFF, b2, bufA, 1024);
    // heads L1 (roles stacked along N): relu(bufA @ hW1p + hb1) -> bufB (no round)
    gemm_tc<0><<<grid, block, SMEM_BYTES>>>(bufA, wp + HW1_OFF, hb1, bufB, 1024);
    // head L2 + tanh + Gaussian log-prob, role-selected
    head2_logprob_kernel<<<M_TOTAL / 8, 256>>>(bufB, role_ids, actions,
                                               hW2, hb2, lsd, out);
}